// round 1
// baseline (speedup 1.0000x reference)
#include <cuda_runtime.h>

// Problem constants (SimplifiedDRN)
#define Bsz  8192
#define INs  1024
#define H1s  2048
#define H2s  2048
#define OUTs 1024
#define Pex  8

// Scratch (device globals: allocation-free per harness rules)
__device__ float g_h1[(size_t)Bsz * H1s];   // 64 MB
__device__ float g_h2[(size_t)Bsz * H2s];   // 64 MB
__device__ float g_p1[(size_t)Bsz * Pex];
__device__ float g_p2[(size_t)Bsz * Pex];

// -------------------------------------------------------------------------
// Selector: probs[b,:] = softmax(x[b,:] @ S + sb), P = 8 experts.
// One warp per row. S is [K, 8] row-major.
// -------------------------------------------------------------------------
__global__ void selector_kernel(const float* __restrict__ X,
                                const float* __restrict__ S,
                                const float* __restrict__ sb,
                                float* __restrict__ probs,
                                int K) {
  int warp = (blockIdx.x * blockDim.x + threadIdx.x) >> 5;
  int lane = threadIdx.x & 31;

  const float4* Xv = reinterpret_cast<const float4*>(X + (size_t)warp * K);
  float acc[8];
#pragma unroll
  for (int p = 0; p < 8; p++) acc[p] = 0.f;

  int nvec = K >> 2;
  for (int v = lane; v < nvec; v += 32) {
    float4 x4 = Xv[v];
    const float4* Sv = reinterpret_cast<const float4*>(S + ((size_t)v << 2) * 8);
    float4 s0 = Sv[0], s1 = Sv[1];   // row i   : cols 0-3, 4-7
    float4 s2 = Sv[2], s3 = Sv[3];   // row i+1
    float4 s4 = Sv[4], s5 = Sv[5];   // row i+2
    float4 s6 = Sv[6], s7 = Sv[7];   // row i+3
    acc[0] += x4.x * s0.x + x4.y * s2.x + x4.z * s4.x + x4.w * s6.x;
    acc[1] += x4.x * s0.y + x4.y * s2.y + x4.z * s4.y + x4.w * s6.y;
    acc[2] += x4.x * s0.z + x4.y * s2.z + x4.z * s4.z + x4.w * s6.z;
    acc[3] += x4.x * s0.w + x4.y * s2.w + x4.z * s4.w + x4.w * s6.w;
    acc[4] += x4.x * s1.x + x4.y * s3.x + x4.z * s5.x + x4.w * s7.x;
    acc[5] += x4.x * s1.y + x4.y * s3.y + x4.z * s5.y + x4.w * s7.y;
    acc[6] += x4.x * s1.z + x4.y * s3.z + x4.z * s5.z + x4.w * s7.z;
    acc[7] += x4.x * s1.w + x4.y * s3.w + x4.z * s5.w + x4.w * s7.w;
  }

#pragma unroll
  for (int off = 16; off; off >>= 1)
#pragma unroll
    for (int p = 0; p < 8; p++)
      acc[p] += __shfl_xor_sync(0xffffffffu, acc[p], off);

  if (lane == 0) {
    float m = -1e30f;
#pragma unroll
    for (int p = 0; p < 8; p++) { acc[p] += sb[p]; m = fmaxf(m, acc[p]); }
    float s = 0.f;
#pragma unroll
    for (int p = 0; p < 8; p++) { acc[p] = __expf(acc[p] - m); s += acc[p]; }
    float inv = 1.f / s;
#pragma unroll
    for (int p = 0; p < 8; p++) probs[(size_t)warp * 8 + p] = acc[p] * inv;
  }
}

// -------------------------------------------------------------------------
// Fused MoE GEMM:
//   MOE:  C[m,n] = act( sum_k probs[m, k>>LOG_IN] * X[m, k & (IN-1)] * W[k,n]
//                       + sum_p probs[m,p] * bias[p,n] )
//   else: C[m,n] = act( sum_k X[m,k] * W[k,n] + bias[n] )
// 128x128x16 tile, 256 threads, 8x8 register micro-tile.
// All dims are multiples of the tile sizes (no bounds checks needed).
// -------------------------------------------------------------------------
template <bool MOE, bool RELU, int LOG_IN>
__global__ __launch_bounds__(256, 2) void gemm_moe_kernel(
    int M, int N, int K,
    const float* __restrict__ X,     // [M, IN] (MOE) or [M, K]
    const float* __restrict__ W,     // [K, N]
    const float* __restrict__ probs, // [M, 8] (MOE) else unused
    const float* __restrict__ bias,  // [8, N] (MOE) else [N]
    float* __restrict__ C)           // [M, N]
{
  constexpr int BM = 128, BN = 128, BK = 16, TM = 8, TN = 8;
  __shared__ float As[BK][BM];
  __shared__ float Bs[BK][BN];

  const int tid = threadIdx.x;
  const int m0 = blockIdx.y * BM;
  const int n0 = blockIdx.x * BN;

  const int tx = tid & 15;   // N direction (16 threads)
  const int ty = tid >> 4;   // M direction (16 threads)

  float acc[TM][TN];
#pragma unroll
  for (int i = 0; i < TM; i++)
#pragma unroll
    for (int j = 0; j < TN; j++) acc[i][j] = 0.f;

  // A tile load mapping: float4 along K. 256 threads cover 128x16 in 2 steps.
  const int aCol  = (tid & 3) * 4;   // k offset within tile: 0,4,8,12
  const int aRow0 = tid >> 2;        // 0..63
  // B tile load mapping: float4 along N. 256 threads cover 16x128 in 2 steps.
  const int bCol  = (tid & 31) * 4;  // 0..124
  const int bRow0 = tid >> 5;        // 0..7

  constexpr int IN_MASK = MOE ? ((1 << LOG_IN) - 1) : 0;
  constexpr int IN_DIM  = MOE ? (1 << LOG_IN) : 0;

  for (int k0 = 0; k0 < K; k0 += BK) {
    // ---- load A tile (probs-scaled on the fly for MOE) ----
#pragma unroll
    for (int r = 0; r < 2; r++) {
      int row = aRow0 + r * 64;
      int gk  = k0 + aCol;
      float4 v;
      if (MOE) {
        int p  = gk >> LOG_IN;
        int xi = gk & IN_MASK;
        v = *reinterpret_cast<const float4*>(&X[(size_t)(m0 + row) * IN_DIM + xi]);
        float pr = probs[(size_t)(m0 + row) * 8 + p];
        v.x *= pr; v.y *= pr; v.z *= pr; v.w *= pr;
      } else {
        v = *reinterpret_cast<const float4*>(&X[(size_t)(m0 + row) * K + gk]);
      }
      As[aCol + 0][row] = v.x;
      As[aCol + 1][row] = v.y;
      As[aCol + 2][row] = v.z;
      As[aCol + 3][row] = v.w;
    }
    // ---- load B tile ----
#pragma unroll
    for (int r = 0; r < 2; r++) {
      int row = bRow0 + r * 8;
      *reinterpret_cast<float4*>(&Bs[row][bCol]) =
          *reinterpret_cast<const float4*>(&W[(size_t)(k0 + row) * N + n0 + bCol]);
    }
    __syncthreads();

    // ---- compute ----
#pragma unroll
    for (int kk = 0; kk < BK; kk++) {
      float a[TM], b[TN];
#pragma unroll
      for (int i = 0; i < TM; i++) a[i] = As[kk][ty * TM + i];
#pragma unroll
      for (int j = 0; j < TN; j++) b[j] = Bs[kk][tx * TN + j];
#pragma unroll
      for (int i = 0; i < TM; i++)
#pragma unroll
        for (int j = 0; j < TN; j++) acc[i][j] += a[i] * b[j];
    }
    __syncthreads();
  }

  // ---- epilogue: bias (+ probs-weighted expert bias), relu, store ----
#pragma unroll
  for (int i = 0; i < TM; i++) {
    int m = m0 + ty * TM + i;
    float pr[8];
    if (MOE) {
#pragma unroll
      for (int p = 0; p < 8; p++) pr[p] = probs[(size_t)m * 8 + p];
    }
#pragma unroll
    for (int j = 0; j < TN; j++) {
      int n = n0 + tx * TN + j;
      float v = acc[i][j];
      if (MOE) {
#pragma unroll
        for (int p = 0; p < 8; p++) v += pr[p] * bias[(size_t)p * N + n];
      } else {
        v += bias[n];
      }
      if (RELU) v = fmaxf(v, 0.f);
      C[(size_t)m * N + n] = v;
    }
  }
}

// -------------------------------------------------------------------------
extern "C" void kernel_launch(void* const* d_in, const int* in_sizes, int n_in,
                              void* d_out, int out_size) {
  const float* x   = (const float*)d_in[0];
  const float* W1  = (const float*)d_in[1];   // [P, IN, H1] == [P*IN, H1]
  const float* b1  = (const float*)d_in[2];   // [P, H1]
  const float* S1  = (const float*)d_in[3];   // [IN, P]
  const float* sb1 = (const float*)d_in[4];   // [P]
  const float* W2  = (const float*)d_in[5];   // [P, H1, H2] == [P*H1, H2]
  const float* b2  = (const float*)d_in[6];   // [P, H2]
  const float* S2  = (const float*)d_in[7];   // [H1, P]
  const float* sb2 = (const float*)d_in[8];   // [P]
  const float* Wc  = (const float*)d_in[9];   // [H2, OUT]
  const float* bc  = (const float*)d_in[10];  // [OUT]
  float* out = (float*)d_out;

  float *h1, *h2, *p1, *p2;
  cudaGetSymbolAddress((void**)&h1, g_h1);
  cudaGetSymbolAddress((void**)&h2, g_h2);
  cudaGetSymbolAddress((void**)&p1, g_p1);
  cudaGetSymbolAddress((void**)&p2, g_p2);

  // Selector 1: probs1 = softmax(x @ S1 + sb1)
  selector_kernel<<<Bsz / 8, 256>>>(x, S1, sb1, p1, INs);

  // Layer 1 as single GEMM: K = P*IN, A(b, p*IN+i) = probs1[b,p]*x[b,i]
  gemm_moe_kernel<true, true, 10>
      <<<dim3(H1s / 128, Bsz / 128), 256>>>(Bsz, H1s, Pex * INs, x, W1, p1, b1, h1);

  // Selector 2: probs2 = softmax(h1 @ S2 + sb2)
  selector_kernel<<<Bsz / 8, 256>>>(h1, S2, sb2, p2, H1s);

  // Layer 2: K = P*H1
  gemm_moe_kernel<true, true, 11>
      <<<dim3(H2s / 128, Bsz / 128), 256>>>(Bsz, H2s, Pex * H1s, h1, W2, p2, b2, h2);

  // Classifier: plain GEMM + bias, no relu
  gemm_moe_kernel<false, false, 0>
      <<<dim3(OUTs / 128, Bsz / 128), 256>>>(Bsz, OUTs, H2s, h2, Wc, nullptr, bc, out);
}

// round 5
// speedup vs baseline: 3.3097x; 3.3097x over previous
#include <cuda_runtime.h>
#include <cstdint>

#define Bsz  8192
#define INs  1024
#define H1s  2048
#define H2s  2048
#define OUTs 1024
#define Pex  8

// Scratch (device globals: allocation-free per harness rules)
__device__ float g_h1[(size_t)Bsz * H1s];          // 64 MB
__device__ float g_h2[(size_t)Bsz * H2s];          // 64 MB
__device__ float g_p1[(size_t)Bsz * Pex];
__device__ float g_p2[(size_t)Bsz * Pex];
__device__ float g_xr[(size_t)Bsz * INs];          // 32 MB  (tf32-rounded x)
__device__ float g_w1r[(size_t)Pex * INs * H1s];   // 64 MB
__device__ float g_w2r[(size_t)Pex * H1s * H2s];   // 128 MB
__device__ float g_wcr[(size_t)H2s * OUTs];        // 8 MB

// ------------------------------ helpers ---------------------------------
__device__ __forceinline__ uint32_t smem_u32(const void* p) {
  uint32_t a;
  asm("{ .reg .u64 t; cvta.to.shared.u64 t, %1; cvt.u32.u64 %0, t; }"
      : "=r"(a) : "l"(p));
  return a;
}
__device__ __forceinline__ void cpa16(uint32_t s, const void* g) {
  asm volatile("cp.async.cg.shared.global [%0], [%1], 16;" :: "r"(s), "l"(g));
}
__device__ __forceinline__ void cpa_commit() {
  asm volatile("cp.async.commit_group;" ::: "memory");
}
template <int N>
__device__ __forceinline__ void cpa_wait() {
  asm volatile("cp.async.wait_group %0;" :: "n"(N) : "memory");
}
__device__ __forceinline__ uint32_t f2tf32(float f) {
  uint32_t u;
  asm("cvt.rna.tf32.f32 %0, %1;" : "=r"(u) : "f"(f));
  return u;
}
__device__ __forceinline__ void ldsm4(uint32_t (&r)[4], uint32_t a) {
  asm volatile("ldmatrix.sync.aligned.m8n8.x4.shared.b16 {%0,%1,%2,%3}, [%4];"
               : "=r"(r[0]), "=r"(r[1]), "=r"(r[2]), "=r"(r[3]) : "r"(a));
}
__device__ __forceinline__ void mma_t(float (&c)[4], const uint32_t (&a)[4],
                                      uint32_t b0, uint32_t b1) {
  asm volatile(
      "mma.sync.aligned.m16n8k8.row.col.f32.tf32.tf32.f32 "
      "{%0,%1,%2,%3}, {%4,%5,%6,%7}, {%8,%9}, {%0,%1,%2,%3};"
      : "+f"(c[0]), "+f"(c[1]), "+f"(c[2]), "+f"(c[3])
      : "r"(a[0]), "r"(a[1]), "r"(a[2]), "r"(a[3]), "r"(b0), "r"(b1));
}

// -------------------------------------------------------------------------
// tf32 pre-round pass (round-to-nearest; makes HW truncation exact)
// -------------------------------------------------------------------------
__global__ void round_tf32_kernel(const float4* __restrict__ in,
                                  float4* __restrict__ out, int n4) {
  int i = blockIdx.x * blockDim.x + threadIdx.x;
  if (i < n4) {
    float4 v = in[i];
    v.x = __uint_as_float(f2tf32(v.x));
    v.y = __uint_as_float(f2tf32(v.y));
    v.z = __uint_as_float(f2tf32(v.z));
    v.w = __uint_as_float(f2tf32(v.w));
    out[i] = v;
  }
}

// -------------------------------------------------------------------------
// Selector: probs[b,:] = softmax(x[b,:] @ S + sb), P = 8. One warp per row.
// -------------------------------------------------------------------------
__global__ void selector_kernel(const float* __restrict__ X,
                                const float* __restrict__ S,
                                const float* __restrict__ sb,
                                float* __restrict__ probs, int K) {
  int warp = (blockIdx.x * blockDim.x + threadIdx.x) >> 5;
  int lane = threadIdx.x & 31;
  const float4* Xv = reinterpret_cast<const float4*>(X + (size_t)warp * K);
  float acc[8];
#pragma unroll
  for (int p = 0; p < 8; p++) acc[p] = 0.f;
  int nvec = K >> 2;
  for (int v = lane; v < nvec; v += 32) {
    float4 x4 = Xv[v];
    const float4* Sv = reinterpret_cast<const float4*>(S + ((size_t)v << 2) * 8);
    float4 s0 = Sv[0], s1 = Sv[1], s2 = Sv[2], s3 = Sv[3];
    float4 s4 = Sv[4], s5 = Sv[5], s6 = Sv[6], s7 = Sv[7];
    acc[0] += x4.x * s0.x + x4.y * s2.x + x4.z * s4.x + x4.w * s6.x;
    acc[1] += x4.x * s0.y + x4.y * s2.y + x4.z * s4.y + x4.w * s6.y;
    acc[2] += x4.x * s0.z + x4.y * s2.z + x4.z * s4.z + x4.w * s6.z;
    acc[3] += x4.x * s0.w + x4.y * s2.w + x4.z * s4.w + x4.w * s6.w;
    acc[4] += x4.x * s1.x + x4.y * s3.x + x4.z * s5.x + x4.w * s7.x;
    acc[5] += x4.x * s1.y + x4.y * s3.y + x4.z * s5.y + x4.w * s7.y;
    acc[6] += x4.x * s1.z + x4.y * s3.z + x4.z * s5.z + x4.w * s7.z;
    acc[7] += x4.x * s1.w + x4.y * s3.w + x4.z * s5.w + x4.w * s7.w;
  }
#pragma unroll
  for (int off = 16; off; off >>= 1)
#pragma unroll
    for (int p = 0; p < 8; p++)
      acc[p] += __shfl_xor_sync(0xffffffffu, acc[p], off);
  if (lane == 0) {
    float m = -1e30f;
#pragma unroll
    for (int p = 0; p < 8; p++) { acc[p] += sb[p]; m = fmaxf(m, acc[p]); }
    float s = 0.f;
#pragma unroll
    for (int p = 0; p < 8; p++) { acc[p] = __expf(acc[p] - m); s += acc[p]; }
    float inv = 1.f / s;
#pragma unroll
    for (int p = 0; p < 8; p++) probs[(size_t)warp * 8 + p] = acc[p] * inv;
  }
}

// -------------------------------------------------------------------------
// mma.sync tf32 GEMM, tile 128x128x32, 3-stage cp.async, 8 warps (64x32 each)
//   MOE: C = act( [probs (.) X expanded over experts] @ W + probs@bias )
//   RR : relu + tf32-round the stored output (hidden layers)
// -------------------------------------------------------------------------
template <bool MOE, bool RR, int LOG_IN>
__global__ __launch_bounds__(256, 2) void tc_gemm(
    int N, int K,
    const float* __restrict__ X, const float* __restrict__ W,
    const float* __restrict__ probs, const float* __restrict__ bias,
    float* __restrict__ C) {
  constexpr int NST = 3;
  constexpr int SSTRIDE_F = 8320;   // floats/stage: A 4096 + B 32*132
  constexpr int BSTART_F = 4096;
  constexpr int BROW_F = 132;
  constexpr int LDA = 1 << LOG_IN;
  constexpr int MASK = LDA - 1;

  extern __shared__ float smf[];
  __shared__ float probs_s[128][8];
  __shared__ float bias_s[8][128];

  const int tid = threadIdx.x, lane = tid & 31, wid = tid >> 5;
  const int wm = wid >> 2, wn = wid & 3;
  const int m0 = blockIdx.y * 128, n0 = blockIdx.x * 128;
  const uint32_t sbase = smem_u32(smf);

  if (MOE) {
    for (int i = tid; i < 1024; i += 256) {
      int r = i >> 3, p = i & 7;
      probs_s[r][p] = probs[(size_t)(m0 + r) * 8 + p];
    }
    for (int i = tid; i < 1024; i += 256) {
      int p = i >> 7, c = i & 127;
      bias_s[p][c] = bias[(size_t)p * N + n0 + c];
    }
  } else {
    if (tid < 128) bias_s[0][tid] = bias[n0 + tid];
  }

  const int nchunk = K >> 5;

  auto issue = [&](int c, int st) {
    const int k0 = c << 5;
    const uint32_t sA = sbase + (uint32_t)st * (SSTRIDE_F * 4);
    const uint32_t sB = sA + BSTART_F * 4;
    const float* ab = X + (k0 & MASK);
#pragma unroll
    for (int i = 0; i < 4; i++) {          // A: 128 x 32, SW128 swizzle
      int f = tid + i * 256;
      int m = f >> 3, g = f & 7;
      cpa16(sA + (uint32_t)(m * 128 + ((g ^ (m & 7)) << 4)),
            ab + (size_t)(m0 + m) * LDA + g * 4);
    }
#pragma unroll
    for (int i = 0; i < 4; i++) {          // B: 32 x 128, pad-132 rows
      int f = tid + i * 256;
      int k = f >> 5, nc = f & 31;
      cpa16(sB + (uint32_t)(k * 528 + nc * 16),
            W + (size_t)(k0 + k) * N + n0 + nc * 4);
    }
    cpa_commit();
  };

  float cacc[4][4][4];
#pragma unroll
  for (int a = 0; a < 4; a++)
#pragma unroll
    for (int b = 0; b < 4; b++)
#pragma unroll
      for (int d = 0; d < 4; d++) cacc[a][b][d] = 0.f;

  // ldmatrix per-thread address components
  const int q = lane >> 3, r8v = lane & 7, qh = q >> 1;
  uint32_t arow[4];
  int arow7[4];
#pragma unroll
  for (int mt = 0; mt < 4; mt++) {
    int r = wm * 64 + mt * 16 + (q & 1) * 8 + r8v;
    arow[mt] = (uint32_t)r * 128u;
    arow7[mt] = r & 7;
  }
  const int grp = lane >> 2, tig = lane & 3;

  float pr_lo[4], pr_hi[4];

  issue(0, 0);
  issue(1, 1);

  int st = 0;
  for (int c = 0; c < nchunk; c++) {
    cpa_wait<1>();
    __syncthreads();
    {
      int cn = c + 2;
      if (cn < nchunk) {
        int stn = st + 2; if (stn >= NST) stn -= NST;
        issue(cn, stn);
      } else {
        cpa_commit();
      }
    }
    if (MOE) {
      if ((c & (MASK >> 5)) == 0) {       // expert boundary: reload probs
        int p = (c << 5) >> LOG_IN;
#pragma unroll
        for (int mt = 0; mt < 4; mt++) {
          int r = wm * 64 + mt * 16 + grp;
          pr_lo[mt] = probs_s[r][p];
          pr_hi[mt] = probs_s[r + 8][p];
        }
      }
    }
    const uint32_t sA = sbase + (uint32_t)st * (SSTRIDE_F * 4);
    const float* sBf = smf + st * SSTRIDE_F + BSTART_F;
#pragma unroll
    for (int ks = 0; ks < 4; ks++) {
      uint32_t af[4][4];
#pragma unroll
      for (int mt = 0; mt < 4; mt++) {
        ldsm4(af[mt], sA + arow[mt] +
                          (uint32_t)(((ks * 2 + qh) ^ arow7[mt]) << 4));
        if (MOE) {
#pragma unroll
          for (int j = 0; j < 4; j++) {
            float v = __uint_as_float(af[mt][j]) *
                      ((j & 1) ? pr_hi[mt] : pr_lo[mt]);
            af[mt][j] = f2tf32(v);
          }
        }
      }
      uint32_t bf[4][2];
#pragma unroll
      for (int nt = 0; nt < 4; nt++) {
        int n = wn * 32 + nt * 8 + grp;
        bf[nt][0] = __float_as_uint(sBf[(ks * 8 + tig) * BROW_F + n]);
        bf[nt][1] = __float_as_uint(sBf[(ks * 8 + tig + 4) * BROW_F + n]);
      }
#pragma unroll
      for (int mt = 0; mt < 4; mt++)
#pragma unroll
        for (int nt = 0; nt < 4; nt++)
          mma_t(cacc[mt][nt], af[mt], bf[nt][0], bf[nt][1]);
    }
    st++; if (st >= NST) st = 0;
  }

  // ---- epilogue ----
#pragma unroll
  for (int mt = 0; mt < 4; mt++) {
#pragma unroll
    for (int half = 0; half < 2; half++) {
      int r = wm * 64 + mt * 16 + grp + half * 8;
      int m = m0 + r;
      float prr[8];
      if (MOE) {
#pragma unroll
        for (int p = 0; p < 8; p++) prr[p] = probs_s[r][p];
      }
#pragma unroll
      for (int nt = 0; nt < 4; nt++) {
        int nloc = wn * 32 + nt * 8 + tig * 2;
        float v0 = cacc[mt][nt][half * 2 + 0];
        float v1 = cacc[mt][nt][half * 2 + 1];
        if (MOE) {
          float cb0 = 0.f, cb1 = 0.f;
#pragma unroll
          for (int p = 0; p < 8; p++) {
            cb0 += prr[p] * bias_s[p][nloc];
            cb1 += prr[p] * bias_s[p][nloc + 1];
          }
          v0 += cb0; v1 += cb1;
        } else {
          v0 += bias_s[0][nloc];
          v1 += bias_s[0][nloc + 1];
        }
        if (RR) {
          v0 = __uint_as_float(f2tf32(fmaxf(v0, 0.f)));
          v1 = __uint_as_float(f2tf32(fmaxf(v1, 0.f)));
        }
        float2 o; o.x = v0; o.y = v1;
        *reinterpret_cast<float2*>(&C[(size_t)m * N + n0 + nloc]) = o;
      }
    }
  }
}

// -------------------------------------------------------------------------
extern "C" void kernel_launch(void* const* d_in, const int* in_sizes, int n_in,
                              void* d_out, int out_size) {
  const float* x   = (const float*)d_in[0];
  const float* W1  = (const float*)d_in[1];
  const float* b1  = (const float*)d_in[2];
  const float* S1  = (const float*)d_in[3];
  const float* sb1 = (const float*)d_in[4];
  const float* W2  = (const float*)d_in[5];
  const float* b2  = (const float*)d_in[6];
  const float* S2  = (const float*)d_in[7];
  const float* sb2 = (const float*)d_in[8];
  const float* Wc  = (const float*)d_in[9];
  const float* bc  = (const float*)d_in[10];
  float* out = (float*)d_out;

  float *h1, *h2, *p1, *p2, *xr, *w1r, *w2r, *wcr;
  cudaGetSymbolAddress((void**)&h1, g_h1);
  cudaGetSymbolAddress((void**)&h2, g_h2);
  cudaGetSymbolAddress((void**)&p1, g_p1);
  cudaGetSymbolAddress((void**)&p2, g_p2);
  cudaGetSymbolAddress((void**)&xr, g_xr);
  cudaGetSymbolAddress((void**)&w1r, g_w1r);
  cudaGetSymbolAddress((void**)&w2r, g_w2r);
  cudaGetSymbolAddress((void**)&wcr, g_wcr);

  const int SMEM_DYN = 3 * 8320 * 4;   // 99840 B
  cudaFuncSetAttribute(tc_gemm<true, true, 10>,
                       cudaFuncAttributeMaxDynamicSharedMemorySize, SMEM_DYN);
  cudaFuncSetAttribute(tc_gemm<true, true, 11>,
                       cudaFuncAttributeMaxDynamicSharedMemorySize, SMEM_DYN);
  cudaFuncSetAttribute(tc_gemm<false, false, 11>,
                       cudaFuncAttributeMaxDynamicSharedMemorySize, SMEM_DYN);

  // tf32 pre-round (RNA) of all GEMM operands
  {
    int n4;
    n4 = (Bsz * INs) / 4;
    round_tf32_kernel<<<n4 / 256, 256>>>((const float4*)x, (float4*)xr, n4);
    n4 = (Pex * INs * H1s) / 4;
    round_tf32_kernel<<<n4 / 256, 256>>>((const float4*)W1, (float4*)w1r, n4);
    n4 = (Pex * H1s * H2s) / 4;
    round_tf32_kernel<<<n4 / 256, 256>>>((const float4*)W2, (float4*)w2r, n4);
    n4 = (H2s * OUTs) / 4;
    round_tf32_kernel<<<n4 / 256, 256>>>((const float4*)Wc, (float4*)wcr, n4);
  }

  // selectors use full-precision activations
  selector_kernel<<<Bsz / 8, 256>>>(x, S1, sb1, p1, INs);
  tc_gemm<true, true, 10><<<dim3(H1s / 128, Bsz / 128), 256, SMEM_DYN>>>(
      H1s, Pex * INs, xr, w1r, p1, b1, h1);

  selector_kernel<<<Bsz / 8, 256>>>(h1, S2, sb2, p2, H1s);
  tc_gemm<true, true, 11><<<dim3(H2s / 128, Bsz / 128), 256, SMEM_DYN>>>(
      H2s, Pex * H1s, h1, w2r, p2, b2, h2);

  tc_gemm<false, false, 11><<<dim3(OUTs / 128, Bsz / 128), 256, SMEM_DYN>>>(
      OUTs, H2s, h2, wcr, nullptr, bc, out);
}